// round 11
// baseline (speedup 1.0000x reference)
#include <cuda_runtime.h>
#include <cuda_bf16.h>
#include <math.h>

#define NN      50000
#define EE      800000
#define ET      (EE + NN)      // edges incl. self loops
#define FIN     128
#define CC      256            // HEADS*HID
#define HEADS   4
#define HID     64
#define NG      500
#define OUTD    128
#define NCLS    2
#define SLOPE   0.2f
#define BNEPS   1e-5f

// ---------------- device scratch (static allocation only) ----------------
__device__ float g_h1 [NN * CC];   // GEMM1 output
__device__ float g_hb1[NN * CC];   // layer1 output (post relu+bn)
__device__ float g_h2 [NN * CC];   // GEMM2 output
__device__ float g_hb2[NN * CC];   // layer2 output (post relu+bn)
__device__ float g_as [NN * HEADS];
__device__ float g_ad [NN * HEADS];
__device__ int   g_rowptr[NN + 1];
__device__ int   g_wcur[NN];
__device__ int   g_col[ET];
__device__ int   g_is64;           // 1 if edge_index/batch are int64, else int32

// ---------------- dtype sniff (deterministic, input-derived) --------------
// int64 node indices are < 50000 << 2^32 -> high 32 bits of every 64-bit word
// are zero. int32 data read as 64-bit words packs two random indices -> high
// word nonzero with prob ~1-1/50000 per sample. 256 samples decide robustly.
__global__ void k_sniff(const void* __restrict__ ei) {
    if (threadIdx.x != 0 || blockIdx.x != 0) return;
    const unsigned long long* p = (const unsigned long long*)ei;
    int nz = 0;
    for (int i = 0; i < 256; i++)
        if ((p[i] >> 32) != 0ull) nz++;
    g_is64 = (nz == 0) ? 1 : 0;
}

__device__ __forceinline__ int load_idx(const void* p, int i) {
    return g_is64 ? (int)((const long long*)p)[i] : ((const int*)p)[i];
}

// ---------------- CSR build ----------------
__global__ void k_zero_counts() {
    int i = blockIdx.x * blockDim.x + threadIdx.x;
    if (i < NN) g_wcur[i] = 0;
}

__global__ void k_count(const void* __restrict__ ei) {
    int i = blockIdx.x * blockDim.x + threadIdx.x;
    if (i >= ET) return;
    int d = (i < EE) ? load_idx(ei, EE + i) : (i - EE);
    atomicAdd(&g_wcur[d], 1);
}

// single block, 1024 threads: exclusive scan of counts -> rowptr; reset wcur to rowptr
__global__ void k_scan2() {
    __shared__ int part[1024];
    const int tid = threadIdx.x;
    const int chunk = (NN + 1023) / 1024;     // 49
    const int start = tid * chunk;
    int local[49];
    int s = 0;
    for (int j = 0; j < chunk; j++) {
        int idx = start + j;
        int c = (idx < NN) ? g_wcur[idx] : 0;
        local[j] = c;
        s += c;
    }
    part[tid] = s;
    __syncthreads();
    for (int off = 1; off < 1024; off <<= 1) {
        int v = (tid >= off) ? part[tid - off] : 0;
        __syncthreads();
        part[tid] += v;
        __syncthreads();
    }
    int run = (tid > 0) ? part[tid - 1] : 0;
    for (int j = 0; j < chunk; j++) {
        int idx = start + j;
        if (idx < NN) {
            g_rowptr[idx] = run;
            g_wcur[idx]   = run;
            run += local[j];
        }
    }
    if (tid == 1023) g_rowptr[NN] = part[1023];
}

__global__ void k_scatter(const void* __restrict__ ei) {
    int i = blockIdx.x * blockDim.x + threadIdx.x;
    if (i >= ET) return;
    int s, d;
    if (i < EE) { s = load_idx(ei, i); d = load_idx(ei, EE + i); }
    else        { s = i - EE;          d = i - EE; }
    int pos = atomicAdd(&g_wcur[d], 1);
    g_col[pos] = s;
}

// ---------------- SGEMM: C[M,N] = A[M,K] @ B[K,N], row-major --------------
// Double-buffered smem pipeline: 1 barrier per K-iter, gmem loads staged
// through registers and overlapped with the FMA block of the previous tile.
// L = 1: A = input x (K=FIN), C = g_h1.   L = 2: A = g_hb1 (K=CC), C = g_h2.
#define BM 128
#define BN 128
#define BKK 16
template <int L>
__global__ __launch_bounds__(256, 2)
void k_sgemm(const float* __restrict__ Ain, const float* __restrict__ B) {
    const float* A = (L == 1) ? Ain : (const float*)g_hb1;
    float*       C = (L == 1) ? (float*)g_h1 : (float*)g_h2;
    const int K = (L == 1) ? FIN : CC;
    const int M = NN, N = CC;

    __shared__ float As[2][BKK][BM];
    __shared__ float Bs[2][BKK][BN];
    const int tid = threadIdx.x;
    const int m0 = blockIdx.x * BM;
    const int n0 = blockIdx.y * BN;
    const int tm = (tid / 16) * 8;
    const int tn = (tid % 16) * 8;

    // per-thread load coordinates (2 float4 each for A and B per tile)
    const int a_row0 = tid >> 2;             // 0..63   (t=0)
    const int a_row1 = (tid + 256) >> 2;     // 64..127 (t=1)
    const int a_quad = (tid & 3) * 4;
    const int b_row0 = tid >> 5;             // 0..7
    const int b_row1 = (tid + 256) >> 5;     // 8..15
    const int b_col  = (tid & 31) * 4;

    float acc[8][8];
#pragma unroll
    for (int i = 0; i < 8; i++)
#pragma unroll
        for (int j = 0; j < 8; j++) acc[i][j] = 0.f;

    // ---- preload tile 0 into buffer 0 ----
    {
        float4 va0 = make_float4(0.f,0.f,0.f,0.f), va1 = va0;
        if (m0 + a_row0 < M) va0 = *(const float4*)(A + (size_t)(m0 + a_row0) * K + a_quad);
        if (m0 + a_row1 < M) va1 = *(const float4*)(A + (size_t)(m0 + a_row1) * K + a_quad);
        As[0][a_quad + 0][a_row0] = va0.x; As[0][a_quad + 1][a_row0] = va0.y;
        As[0][a_quad + 2][a_row0] = va0.z; As[0][a_quad + 3][a_row0] = va0.w;
        As[0][a_quad + 0][a_row1] = va1.x; As[0][a_quad + 1][a_row1] = va1.y;
        As[0][a_quad + 2][a_row1] = va1.z; As[0][a_quad + 3][a_row1] = va1.w;
        float4 vb0 = *(const float4*)(B + (size_t)b_row0 * N + n0 + b_col);
        float4 vb1 = *(const float4*)(B + (size_t)b_row1 * N + n0 + b_col);
        *(float4*)&Bs[0][b_row0][b_col] = vb0;
        *(float4*)&Bs[0][b_row1][b_col] = vb1;
    }
    __syncthreads();

    int buf = 0;
    for (int k0 = 0; k0 < K; k0 += BKK) {
        const int knext = k0 + BKK;
        float4 va0, va1, vb0, vb1;
        const bool more = (knext < K);
        if (more) {
            va0 = make_float4(0.f,0.f,0.f,0.f); va1 = va0;
            if (m0 + a_row0 < M) va0 = *(const float4*)(A + (size_t)(m0 + a_row0) * K + knext + a_quad);
            if (m0 + a_row1 < M) va1 = *(const float4*)(A + (size_t)(m0 + a_row1) * K + knext + a_quad);
            vb0 = *(const float4*)(B + (size_t)(knext + b_row0) * N + n0 + b_col);
            vb1 = *(const float4*)(B + (size_t)(knext + b_row1) * N + n0 + b_col);
        }
        // compute on current buffer
#pragma unroll
        for (int kk = 0; kk < BKK; kk++) {
            float ra[8], rb[8];
            *(float4*)(ra)     = *(const float4*)&As[buf][kk][tm];
            *(float4*)(ra + 4) = *(const float4*)&As[buf][kk][tm + 4];
            *(float4*)(rb)     = *(const float4*)&Bs[buf][kk][tn];
            *(float4*)(rb + 4) = *(const float4*)&Bs[buf][kk][tn + 4];
#pragma unroll
            for (int i = 0; i < 8; i++)
#pragma unroll
                for (int j = 0; j < 8; j++)
                    acc[i][j] = fmaf(ra[i], rb[j], acc[i][j]);
        }
        if (more) {
            const int nb = buf ^ 1;
            As[nb][a_quad + 0][a_row0] = va0.x; As[nb][a_quad + 1][a_row0] = va0.y;
            As[nb][a_quad + 2][a_row0] = va0.z; As[nb][a_quad + 3][a_row0] = va0.w;
            As[nb][a_quad + 0][a_row1] = va1.x; As[nb][a_quad + 1][a_row1] = va1.y;
            As[nb][a_quad + 2][a_row1] = va1.z; As[nb][a_quad + 3][a_row1] = va1.w;
            *(float4*)&Bs[nb][b_row0][b_col] = vb0;
            *(float4*)&Bs[nb][b_row1][b_col] = vb1;
            __syncthreads();
            buf = nb;
        }
    }

#pragma unroll
    for (int i = 0; i < 8; i++) {
        int gm = m0 + tm + i;
        if (gm < M) {
            *(float4*)(C + (size_t)gm * N + n0 + tn)     = *(float4*)&acc[i][0];
            *(float4*)(C + (size_t)gm * N + n0 + tn + 4) = *(float4*)&acc[i][4];
        }
    }
}

// ---------------- attention dot products: g_as[n,h], g_ad[n,h] ------------
template <int L>
__global__ void k_att(const float* __restrict__ asrc, const float* __restrict__ adst) {
    const float* h = (L == 1) ? (const float*)g_h1 : (const float*)g_h2;
    int warp = (blockIdx.x * blockDim.x + threadIdx.x) >> 5;
    int lane = threadIdx.x & 31;
    if (warp >= NN) return;
    const float4* hp = (const float4*)(h + (size_t)warp * CC + lane * 8);
    float4 v0 = hp[0], v1 = hp[1];
    const float4* ap = (const float4*)(asrc + lane * 8);
    float4 s0 = ap[0], s1 = ap[1];
    const float4* dp = (const float4*)(adst + lane * 8);
    float4 d0 = dp[0], d1 = dp[1];
    float ps = v0.x * s0.x + v0.y * s0.y + v0.z * s0.z + v0.w * s0.w
             + v1.x * s1.x + v1.y * s1.y + v1.z * s1.z + v1.w * s1.w;
    float pd = v0.x * d0.x + v0.y * d0.y + v0.z * d0.z + v0.w * d0.w
             + v1.x * d1.x + v1.y * d1.y + v1.z * d1.z + v1.w * d1.w;
    // reduce within each 8-lane group (one head = 64 channels = 8 lanes)
#pragma unroll
    for (int o = 4; o > 0; o >>= 1) {
        ps += __shfl_xor_sync(0xffffffffu, ps, o);
        pd += __shfl_xor_sync(0xffffffffu, pd, o);
    }
    if ((lane & 7) == 0) {
        g_as[warp * HEADS + (lane >> 3)] = ps;
        g_ad[warp * HEADS + (lane >> 3)] = pd;
    }
}

// ---------------- GAT gather + softmax + bias + relu + BN -----------------
__device__ __forceinline__ float lrelu(float x) {
    return fmaxf(x, 0.f) + SLOPE * fminf(x, 0.f);
}

template <int L>
__global__ __launch_bounds__(256)
void k_gather(const float* __restrict__ bias,
              const float* __restrict__ bg, const float* __restrict__ bb,
              const float* __restrict__ brm, const float* __restrict__ brv) {
    const float* h   = (L == 1) ? (const float*)g_h1  : (const float*)g_h2;
    float*       out = (L == 1) ? (float*)g_hb1 : (float*)g_hb2;
    const float* as  = (const float*)g_as;
    const float* ad  = (const float*)g_ad;

    int warp = (blockIdx.x * blockDim.x + threadIdx.x) >> 5;
    int lane = threadIdx.x & 31;
    if (warp >= NN) return;
    const int d = warp;
    const int beg = g_rowptr[d], end = g_rowptr[d + 1];
    float4 adv = *(const float4*)(ad + d * HEADS);

    // pass 1: per-head max over incoming edges (lane-strided)
    float m0 = -1e30f, m1 = -1e30f, m2 = -1e30f, m3 = -1e30f;
    for (int i = beg + lane; i < end; i += 32) {
        int s = g_col[i];
        float4 av = *(const float4*)(as + s * HEADS);
        m0 = fmaxf(m0, lrelu(av.x + adv.x));
        m1 = fmaxf(m1, lrelu(av.y + adv.y));
        m2 = fmaxf(m2, lrelu(av.z + adv.z));
        m3 = fmaxf(m3, lrelu(av.w + adv.w));
    }
#pragma unroll
    for (int o = 16; o > 0; o >>= 1) {
        m0 = fmaxf(m0, __shfl_xor_sync(0xffffffffu, m0, o));
        m1 = fmaxf(m1, __shfl_xor_sync(0xffffffffu, m1, o));
        m2 = fmaxf(m2, __shfl_xor_sync(0xffffffffu, m2, o));
        m3 = fmaxf(m3, __shfl_xor_sync(0xffffffffu, m3, o));
    }
    const int hidx = lane >> 3;                   // head owning this lane's channels
    float mx_h = (hidx == 0) ? m0 : (hidx == 1) ? m1 : (hidx == 2) ? m2 : m3;
    float ad_h = (hidx == 0) ? adv.x : (hidx == 1) ? adv.y : (hidx == 2) ? adv.z : adv.w;

    // pass 2: edges 2-way unrolled (independent chains -> 2x memory-level
    // parallelism on the col->as->h dependency), lanes parallel over channels.
    float acc[8];
#pragma unroll
    for (int j = 0; j < 8; j++) acc[j] = 0.f;
    float den = 0.f;
    int i = beg;
    for (; i + 1 < end; i += 2) {
        const int sA = g_col[i];
        const int sB = g_col[i + 1];
        const float aA = as[sA * HEADS + hidx];
        const float aB = as[sB * HEADS + hidx];
        const float exA = __expf(lrelu(aA + ad_h) - mx_h);
        const float exB = __expf(lrelu(aB + ad_h) - mx_h);
        if ((lane & 7) == 0) den += exA + exB;
        const float4* hpA = (const float4*)(h + (size_t)sA * CC + lane * 8);
        const float4* hpB = (const float4*)(h + (size_t)sB * CC + lane * 8);
        float4 a0 = hpA[0], a1 = hpA[1];
        float4 b0 = hpB[0], b1 = hpB[1];
        acc[0] = fmaf(exA, a0.x, fmaf(exB, b0.x, acc[0]));
        acc[1] = fmaf(exA, a0.y, fmaf(exB, b0.y, acc[1]));
        acc[2] = fmaf(exA, a0.z, fmaf(exB, b0.z, acc[2]));
        acc[3] = fmaf(exA, a0.w, fmaf(exB, b0.w, acc[3]));
        acc[4] = fmaf(exA, a1.x, fmaf(exB, b1.x, acc[4]));
        acc[5] = fmaf(exA, a1.y, fmaf(exB, b1.y, acc[5]));
        acc[6] = fmaf(exA, a1.z, fmaf(exB, b1.z, acc[6]));
        acc[7] = fmaf(exA, a1.w, fmaf(exB, b1.w, acc[7]));
    }
    if (i < end) {
        const int s = g_col[i];
        const float a = as[s * HEADS + hidx];
        const float ex = __expf(lrelu(a + ad_h) - mx_h);
        if ((lane & 7) == 0) den += ex;
        const float4* hp = (const float4*)(h + (size_t)s * CC + lane * 8);
        float4 v0 = hp[0], v1 = hp[1];
        acc[0] = fmaf(ex, v0.x, acc[0]);
        acc[1] = fmaf(ex, v0.y, acc[1]);
        acc[2] = fmaf(ex, v0.z, acc[2]);
        acc[3] = fmaf(ex, v0.w, acc[3]);
        acc[4] = fmaf(ex, v1.x, acc[4]);
        acc[5] = fmaf(ex, v1.y, acc[5]);
        acc[6] = fmaf(ex, v1.z, acc[6]);
        acc[7] = fmaf(ex, v1.w, acc[7]);
    }
    float denf = __shfl_sync(0xffffffffu, den, hidx << 3);
    float inv = 1.f / denf;
#pragma unroll
    for (int j = 0; j < 8; j++) {
        int c = lane * 8 + j;
        float v = acc[j] * inv + bias[c];
        v = fmaxf(v, 0.f);                                         // ReLU
        v = (v - brm[c]) * rsqrtf(brv[c] + BNEPS) * bg[c] + bb[c]; // BN eval
        out[(size_t)d * CC + c] = v;
    }
}

// ---------------- global mean pool + MLP head -----------------------------
__global__ __launch_bounds__(128)
void k_pool_mlp(const void* __restrict__ batch,
                const float* __restrict__ lw1, const float* __restrict__ lb1,
                const float* __restrict__ lw2, const float* __restrict__ lb2,
                float* __restrict__ out) {
    const float* hb = (const float*)g_hb2;
    const int g = blockIdx.x;
    const int tid = threadIdx.x;
    __shared__ float pooled[CC];
    __shared__ float z[OUTD];
    // node range of graph g in the sorted batch array
    int lo = 0, hi = NN;
    while (lo < hi) { int mid = (lo + hi) >> 1; if (load_idx(batch, mid) < g) lo = mid + 1; else hi = mid; }
    int beg = lo;
    lo = beg; hi = NN;
    while (lo < hi) { int mid = (lo + hi) >> 1; if (load_idx(batch, mid) < g + 1) lo = mid + 1; else hi = mid; }
    int end = lo;
    float s0 = 0.f, s1 = 0.f;
    for (int n = beg; n < end; n++) {
        s0 += hb[(size_t)n * CC + tid];
        s1 += hb[(size_t)n * CC + tid + 128];
    }
    float inv = 1.f / fmaxf((float)(end - beg), 1.f);
    pooled[tid]       = s0 * inv;
    pooled[tid + 128] = s1 * inv;
    __syncthreads();
    float a = lb1[tid];
    for (int k = 0; k < CC; k++) a = fmaf(pooled[k], lw1[k * OUTD + tid], a);
    z[tid] = fmaxf(a, 0.f);
    __syncthreads();
    if (tid < NCLS) {
        float o = lb2[tid];
        for (int k = 0; k < OUTD; k++) o = fmaf(z[k], lw2[k * NCLS + tid], o);
        out[g * NCLS + tid] = o;
    }
}

// ---------------- launch (kernel launches ONLY — no host CUDA API) --------
extern "C" void kernel_launch(void* const* d_in, const int* in_sizes, int n_in,
                              void* d_out, int out_size) {
    const float* x    = (const float*)d_in[0];
    const void*  ei   = d_in[1];     // int32 or int64 -> sniffed on device
    const void*  batch= d_in[2];     // same dtype as ei
    const float* W1  = (const float*)d_in[3];
    const float* as1 = (const float*)d_in[4];
    const float* ad1 = (const float*)d_in[5];
    const float* b1  = (const float*)d_in[6];
    const float* g1  = (const float*)d_in[7];
    const float* be1 = (const float*)d_in[8];
    const float* rm1 = (const float*)d_in[9];
    const float* rv1 = (const float*)d_in[10];
    const float* W2  = (const float*)d_in[11];
    const float* as2 = (const float*)d_in[12];
    const float* ad2 = (const float*)d_in[13];
    const float* b2  = (const float*)d_in[14];
    const float* g2  = (const float*)d_in[15];
    const float* be2 = (const float*)d_in[16];
    const float* rm2 = (const float*)d_in[17];
    const float* rv2 = (const float*)d_in[18];
    const float* lw1 = (const float*)d_in[19];
    const float* lb1 = (const float*)d_in[20];
    const float* lw2 = (const float*)d_in[21];
    const float* lb2 = (const float*)d_in[22];
    float* out = (float*)d_out;

    // dtype sniff + CSR build (reused by both layers)
    k_sniff<<<1, 32>>>(ei);
    k_zero_counts<<<(NN + 255) / 256, 256>>>();
    k_count<<<(ET + 255) / 256, 256>>>(ei);
    k_scan2<<<1, 1024>>>();
    k_scatter<<<(ET + 255) / 256, 256>>>(ei);

    dim3 ggrid((NN + BM - 1) / BM, CC / BN);
    const int nwarp_blocks = (NN * 32 + 255) / 256;

    // Layer 1
    k_sgemm<1><<<ggrid, 256>>>(x, W1);
    k_att<1><<<nwarp_blocks, 256>>>(as1, ad1);
    k_gather<1><<<nwarp_blocks, 256>>>(b1, g1, be1, rm1, rv1);

    // Layer 2
    k_sgemm<2><<<ggrid, 256>>>(nullptr, W2);
    k_att<2><<<nwarp_blocks, 256>>>(as2, ad2);
    k_gather<2><<<nwarp_blocks, 256>>>(b2, g2, be2, rm2, rv2);

    // Pool + MLP
    k_pool_mlp<<<NG, 128>>>(batch, lw1, lb1, lw2, lb2, out);
}